// round 1
// baseline (speedup 1.0000x reference)
#include <cuda_runtime.h>
#include <math.h>

#define Bq   8
#define Tq   2048
#define DINq 512
#define Dq   1024
#define Mq   (Bq*Tq)   // 16384

// Scratch (static device globals — no runtime allocation).
__device__ float g_a[(size_t)Mq * Dq];   // a_step
__device__ float g_b[(size_t)Mq * Dq];   // b_step

// ---------- packed f32x2 helpers (Blackwell dual-FMA pipe) ----------
__device__ __forceinline__ unsigned long long ffma2(unsigned long long a,
                                                    unsigned long long b,
                                                    unsigned long long c) {
    unsigned long long d;
    asm("fma.rn.f32x2 %0, %1, %2, %3;" : "=l"(d) : "l"(a), "l"(b), "l"(c));
    return d;
}
__device__ __forceinline__ unsigned long long pack2(float x, float y) {
    unsigned long long r;
    asm("mov.b64 %0, {%1, %2};" : "=l"(r) : "f"(x), "f"(y));
    return r;
}
__device__ __forceinline__ void unpack2(unsigned long long r, float& x, float& y) {
    asm("mov.b64 {%0, %1}, %2;" : "=f"(x), "=f"(y) : "l"(r));
}

// ---------- fused dual GEMM + discretization epilogue ----------
// Block tile: 128 (M) x 64 (N), BK=16, 256 threads, thread tile 8x4 per GEMM.
#define BM 128
#define BN 64
#define BK 16

__global__ __launch_bounds__(256) void fused_gemm_kernel(
    const float* __restrict__ x,   // [M, DIN]
    const float* __restrict__ Wd,  // [DIN, D]
    const float* __restrict__ bd,  // [D]
    const float* __restrict__ Wb,  // [DIN, D]
    const float* __restrict__ bb,  // [D]
    const float* __restrict__ A_log)
{
    __shared__ float As[BK][BM];
    __shared__ float Wds[BK][BN];
    __shared__ float Wbs[BK][BN];

    const int tid = threadIdx.x;
    const int tx = tid & 15;      // N direction (4 cols each)
    const int ty = tid >> 4;      // M direction (8 rows each)
    const int m0 = blockIdx.y * BM;
    const int n0 = blockIdx.x * BN;

    unsigned long long accd[8][2], accb[8][2];
#pragma unroll
    for (int i = 0; i < 8; i++) {
        accd[i][0] = 0ull; accd[i][1] = 0ull;
        accb[i][0] = 0ull; accb[i][1] = 0ull;
    }

    for (int k0 = 0; k0 < DINq; k0 += BK) {
        // stage x tile (transposed into [k][m])
#pragma unroll
        for (int i = 0; i < 2; i++) {
            int idx = tid + i * 256;
            int m = idx >> 2;
            int kq = (idx & 3) * 4;
            float4 v = *(const float4*)&x[(size_t)(m0 + m) * DINq + k0 + kq];
            As[kq + 0][m] = v.x; As[kq + 1][m] = v.y;
            As[kq + 2][m] = v.z; As[kq + 3][m] = v.w;
        }
        // stage W tiles
        {
            int k = tid >> 4;
            int nq = (tid & 15) * 4;
            *(float4*)&Wds[k][nq] = *(const float4*)&Wd[(size_t)(k0 + k) * Dq + n0 + nq];
            *(float4*)&Wbs[k][nq] = *(const float4*)&Wb[(size_t)(k0 + k) * Dq + n0 + nq];
        }
        __syncthreads();

#pragma unroll
        for (int k = 0; k < BK; k++) {
            float ra[8];
            *(float4*)&ra[0] = *(const float4*)&As[k][ty * 8];
            *(float4*)&ra[4] = *(const float4*)&As[k][ty * 8 + 4];
            float4 wd4 = *(const float4*)&Wds[k][tx * 4];
            float4 wb4 = *(const float4*)&Wbs[k][tx * 4];
            unsigned long long d0 = pack2(wd4.x, wd4.y), d1 = pack2(wd4.z, wd4.w);
            unsigned long long b0 = pack2(wb4.x, wb4.y), b1 = pack2(wb4.z, wb4.w);
#pragma unroll
            for (int i = 0; i < 8; i++) {
                unsigned long long a2 = pack2(ra[i], ra[i]);
                accd[i][0] = ffma2(a2, d0, accd[i][0]);
                accd[i][1] = ffma2(a2, d1, accd[i][1]);
                accb[i][0] = ffma2(a2, b0, accb[i][0]);
                accb[i][1] = ffma2(a2, b1, accb[i][1]);
            }
        }
        __syncthreads();
    }

    // epilogue: delta = softplus(xWd + bd); a = exp(-delta*exp(A_log)); b = delta*(xWb + bb)
    float bdv[4], bbv[4], Av[4];
#pragma unroll
    for (int j = 0; j < 4; j++) {
        int n = n0 + tx * 4 + j;
        bdv[j] = bd[n];
        bbv[j] = bb[n];
        Av[j] = expf(A_log[n]);
    }
#pragma unroll
    for (int i = 0; i < 8; i++) {
        int m = m0 + ty * 8 + i;
        float dd[4], bo[4];
        unpack2(accd[i][0], dd[0], dd[1]); unpack2(accd[i][1], dd[2], dd[3]);
        unpack2(accb[i][0], bo[0], bo[1]); unpack2(accb[i][1], bo[2], bo[3]);
        float av[4], bsv[4];
#pragma unroll
        for (int j = 0; j < 4; j++) {
            float z = dd[j] + bdv[j];
            // numerically stable softplus matching jax.nn.softplus
            float delta = (z > 0.f) ? (z + log1pf(expf(-z))) : log1pf(expf(z));
            av[j] = expf(-delta * Av[j]);
            bsv[j] = delta * (bo[j] + bbv[j]);
        }
        size_t off = (size_t)m * Dq + n0 + tx * 4;
        *(float4*)&g_a[off] = make_float4(av[0], av[1], av[2], av[3]);
        *(float4*)&g_b[off] = make_float4(bsv[0], bsv[1], bsv[2], bsv[3]);
    }
}

// ---------- sequential spiking scan (8192 independent channels) ----------
__global__ __launch_bounds__(256) void scan_kernel(
    const float* __restrict__ thr,
    float* __restrict__ h_out,      // d_out[0 : M*D)  (pre-LN h_post)
    float* __restrict__ s_out)      // d_out[M*D : 2*M*D)
{
    int c = blockIdx.x * blockDim.x + threadIdx.x;  // 0 .. B*D-1
    int b = c / Dq;
    int d = c - b * Dq;
    size_t base = (size_t)b * Tq * Dq + d;
    float th = thr[d];
    float h = 0.f;
#pragma unroll 8
    for (int t = 0; t < Tq; t++) {
        size_t o = base + (size_t)t * Dq;
        float a = g_a[o];
        float bv = g_b[o];
        h = fmaf(a, h, bv);
        bool sp = (h > th);
        float s = sp ? 1.f : 0.f;
        h = sp ? 0.f : h;
        h_out[o] = h;
        s_out[o] = s;
    }
}

// ---------- LayerNorm over D (in place on d_out first half) ----------
__global__ __launch_bounds__(256) void ln_kernel(
    const float* __restrict__ gamma,
    const float* __restrict__ beta,
    float* __restrict__ out)
{
    const int row = blockIdx.x;
    const int tid = threadIdx.x;
    size_t off = (size_t)row * Dq + tid * 4;
    float4 v = *(float4*)&out[off];

    __shared__ float red[256];
    float s = v.x + v.y + v.z + v.w;
    red[tid] = s;
    __syncthreads();
#pragma unroll
    for (int st = 128; st > 0; st >>= 1) {
        if (tid < st) red[tid] += red[tid + st];
        __syncthreads();
    }
    float mu = red[0] * (1.f / Dq);
    __syncthreads();

    float d0 = v.x - mu, d1 = v.y - mu, d2 = v.z - mu, d3 = v.w - mu;
    red[tid] = d0 * d0 + d1 * d1 + d2 * d2 + d3 * d3;
    __syncthreads();
#pragma unroll
    for (int st = 128; st > 0; st >>= 1) {
        if (tid < st) red[tid] += red[tid + st];
        __syncthreads();
    }
    float rstd = rsqrtf(red[0] * (1.f / Dq) + 1e-5f);

    int d = tid * 4;
    float4 g = *(const float4*)&gamma[d];
    float4 be = *(const float4*)&beta[d];
    float4 o;
    o.x = d0 * rstd * g.x + be.x;
    o.y = d1 * rstd * g.y + be.y;
    o.z = d2 * rstd * g.z + be.z;
    o.w = d3 * rstd * g.w + be.w;
    *(float4*)&out[off] = o;
}

extern "C" void kernel_launch(void* const* d_in, const int* in_sizes, int n_in,
                              void* d_out, int out_size)
{
    const float* x     = (const float*)d_in[0];
    const float* Wd    = (const float*)d_in[1];
    const float* bd    = (const float*)d_in[2];
    const float* Wb    = (const float*)d_in[3];
    const float* bb    = (const float*)d_in[4];
    const float* A_log = (const float*)d_in[5];
    const float* thr   = (const float*)d_in[6];
    const float* gamma = (const float*)d_in[7];
    const float* beta  = (const float*)d_in[8];

    float* out    = (float*)d_out;                    // [B,T,D] normalized output
    float* spikes = out + (size_t)Mq * Dq;            // [B,T,D] spikes

    dim3 grid(Dq / BN, Mq / BM);                      // (16, 128)
    fused_gemm_kernel<<<grid, 256>>>(x, Wd, bd, Wb, bb, A_log);
    scan_kernel<<<(Bq * Dq) / 256, 256>>>(thr, out, spikes);
    ln_kernel<<<Mq, 256>>>(gamma, beta, out);
}

// round 4
// speedup vs baseline: 1.1948x; 1.1948x over previous
#include <cuda_runtime.h>
#include <math.h>
#include <stdint.h>

#define Bq   8
#define Tq   2048
#define DINq 512
#define Dq   1024
#define Mq   (Bq*Tq)   // 16384

typedef unsigned long long ull;

// Scratch (static device global — no runtime allocation).
__device__ float2 g_ab[(size_t)Mq * Dq];   // (a_step, b_step) interleaved

// ---------- packed f32x2 helpers (Blackwell dual-FMA pipe) ----------
__device__ __forceinline__ ull ffma2(ull a, ull b, ull c) {
    ull d;
    asm("fma.rn.f32x2 %0, %1, %2, %3;" : "=l"(d) : "l"(a), "l"(b), "l"(c));
    return d;
}
__device__ __forceinline__ ull pk2(float x, float y) {
    ull r;
    asm("mov.b64 %0, {%1, %2};" : "=l"(r) : "f"(x), "f"(y));
    return r;
}
__device__ __forceinline__ ull dup2(float x) {
    ull r;
    asm("mov.b64 %0, {%1, %1};" : "=l"(r) : "f"(x));
    return r;
}
__device__ __forceinline__ void upk2(ull r, float& x, float& y) {
    asm("mov.b64 {%0, %1}, %2;" : "=f"(x), "=f"(y) : "l"(r));
}

// ---------- fused dual GEMM + discretization epilogue ----------
// CTA tile 128(M) x 64(N), BK=16, 256 threads, thread tile 8x4 per GEMM.
// Register-staged LDG + double-buffered smem: one __syncthreads per chunk.
#define BM 128
#define BN 64
#define BK 16
#define BMp 132
#define CHUNKS (DINq / BK)   // 32

__global__ __launch_bounds__(256, 2) void fused_gemm_kernel(
    const float* __restrict__ x,   // [M, DIN]
    const float* __restrict__ Wd,  // [DIN, D]
    const float* __restrict__ bd,  // [D]
    const float* __restrict__ Wb,  // [DIN, D]
    const float* __restrict__ bb,  // [D]
    const float* __restrict__ A_log)
{
    __shared__ float As[2][BK][BMp];
    __shared__ float Wds[2][BK][BN];
    __shared__ float Wbs[2][BK][BN];

    const int tid = threadIdx.x;
    const int tx = tid & 15;       // N direction (4 cols each)
    const int ty = tid >> 4;       // M direction (8 rows each)
    const int n0 = blockIdx.x * BN;
    const int m0 = blockIdx.y * BM;

    // copy assignments
    const int xr = tid >> 2, xl4 = tid & 3;          // x rows 0..63 (+64), k-quad
    const float* xp0 = x + (size_t)(m0 + xr) * DINq + xl4 * 4;
    const float* xp1 = x + (size_t)(m0 + 64 + xr) * DINq + xl4 * 4;
    const int wk = tid >> 4, wl4 = tid & 15;         // W row k, n-quad
    const float* wdp = Wd + (size_t)wk * Dq + n0 + wl4 * 4;
    const float* wbp = Wb + (size_t)wk * Dq + n0 + wl4 * 4;

    ull accd[8][2], accb[8][2];
#pragma unroll
    for (int i = 0; i < 8; i++) {
        accd[i][0] = 0ull; accd[i][1] = 0ull;
        accb[i][0] = 0ull; accb[i][1] = 0ull;
    }

    // prologue: fetch + stage chunk 0 into buffer 0
    float4 rx0 = *(const float4*)xp0;
    float4 rx1 = *(const float4*)xp1;
    float4 rwd = *(const float4*)wdp;
    float4 rwb = *(const float4*)wbp;
    {
        const int kq = xl4 * 4;
        As[0][kq + 0][xr] = rx0.x; As[0][kq + 1][xr] = rx0.y;
        As[0][kq + 2][xr] = rx0.z; As[0][kq + 3][xr] = rx0.w;
        As[0][kq + 0][64 + xr] = rx1.x; As[0][kq + 1][64 + xr] = rx1.y;
        As[0][kq + 2][64 + xr] = rx1.z; As[0][kq + 3][64 + xr] = rx1.w;
        *(float4*)&Wds[0][wk][wl4 * 4] = rwd;
        *(float4*)&Wbs[0][wk][wl4 * 4] = rwb;
    }
    __syncthreads();

    int st = 0;
    for (int c = 0; c < CHUNKS; c++) {
        // issue next chunk's global loads (hidden under compute)
        if (c + 1 < CHUNKS) {
            const int ko = (c + 1) * BK;
            rx0 = *(const float4*)(xp0 + ko);
            rx1 = *(const float4*)(xp1 + ko);
            rwd = *(const float4*)(wdp + (size_t)ko * Dq);
            rwb = *(const float4*)(wbp + (size_t)ko * Dq);
        }

#pragma unroll
        for (int k = 0; k < BK; k++) {
            float4 a0 = *(const float4*)&As[st][k][ty * 8];
            float4 a1 = *(const float4*)&As[st][k][ty * 8 + 4];
            float4 wd4 = *(const float4*)&Wds[st][k][tx * 4];
            float4 wb4 = *(const float4*)&Wbs[st][k][tx * 4];
            ull d0 = pk2(wd4.x, wd4.y), d1 = pk2(wd4.z, wd4.w);
            ull b0 = pk2(wb4.x, wb4.y), b1 = pk2(wb4.z, wb4.w);
            float am[8] = {a0.x, a0.y, a0.z, a0.w, a1.x, a1.y, a1.z, a1.w};
#pragma unroll
            for (int i = 0; i < 8; i++) {
                ull a2 = dup2(am[i]);
                accd[i][0] = ffma2(a2, d0, accd[i][0]);
                accd[i][1] = ffma2(a2, d1, accd[i][1]);
                accb[i][0] = ffma2(a2, b0, accb[i][0]);
                accb[i][1] = ffma2(a2, b1, accb[i][1]);
            }
        }

        // stage next chunk into the other buffer
        if (c + 1 < CHUNKS) {
            const int ns = st ^ 1;
            const int kq = xl4 * 4;
            As[ns][kq + 0][xr] = rx0.x; As[ns][kq + 1][xr] = rx0.y;
            As[ns][kq + 2][xr] = rx0.z; As[ns][kq + 3][xr] = rx0.w;
            As[ns][kq + 0][64 + xr] = rx1.x; As[ns][kq + 1][64 + xr] = rx1.y;
            As[ns][kq + 2][64 + xr] = rx1.z; As[ns][kq + 3][64 + xr] = rx1.w;
            *(float4*)&Wds[ns][wk][wl4 * 4] = rwd;
            *(float4*)&Wbs[ns][wk][wl4 * 4] = rwb;
            __syncthreads();
            st = ns;
        }
    }

    // epilogue: delta = softplus(xWd+bd); a = exp(-delta*exp(A_log)); b = delta*(xWb+bb)
    float bdv[4], bbv[4], Av[4];
#pragma unroll
    for (int j = 0; j < 4; j++) {
        int n = n0 + tx * 4 + j;
        bdv[j] = __ldg(&bd[n]);
        bbv[j] = __ldg(&bb[n]);
        Av[j] = expf(__ldg(&A_log[n]));
    }
#pragma unroll
    for (int i = 0; i < 8; i++) {
        int m = m0 + ty * 8 + i;
        float dd[4], bo[4];
        upk2(accd[i][0], dd[0], dd[1]); upk2(accd[i][1], dd[2], dd[3]);
        upk2(accb[i][0], bo[0], bo[1]); upk2(accb[i][1], bo[2], bo[3]);
        float2 o[4];
#pragma unroll
        for (int j = 0; j < 4; j++) {
            float z = dd[j] + bdv[j];
            float delta = (z > 0.f) ? (z + log1pf(expf(-z))) : log1pf(expf(z));
            o[j].x = expf(-delta * Av[j]);
            o[j].y = delta * (bo[j] + bbv[j]);
        }
        float2* dst = &g_ab[(size_t)m * Dq + n0 + tx * 4];
        *(float4*)(dst + 0) = *(const float4*)(o + 0);
        *(float4*)(dst + 2) = *(const float4*)(o + 2);
    }
}

// ---------- sequential spiking scan (8192 independent channels) ----------
__global__ __launch_bounds__(32) void scan_kernel(
    const float* __restrict__ thr,
    float* __restrict__ h_out, float* __restrict__ s_out)
{
    const int c = blockIdx.x * 32 + threadIdx.x;   // 0 .. B*D-1
    const int b = c >> 10;
    const int d = c & 1023;
    const size_t base = (size_t)b * Tq * Dq + d;
    const float th = thr[d];
    float h = 0.f;
    for (int t0 = 0; t0 < Tq; t0 += 16) {
        float2 v[16];
#pragma unroll
        for (int j = 0; j < 16; j++) v[j] = g_ab[base + (size_t)(t0 + j) * Dq];
#pragma unroll
        for (int j = 0; j < 16; j++) {
            h = fmaf(v[j].x, h, v[j].y);
            const bool sp = (h > th);
            const size_t o = base + (size_t)(t0 + j) * Dq;
            s_out[o] = sp ? 1.f : 0.f;
            h = sp ? 0.f : h;
            h_out[o] = h;
        }
    }
}

// ---------- LayerNorm over D (in place on d_out first half) ----------
__global__ __launch_bounds__(256) void ln_kernel(
    const float* __restrict__ gamma, const float* __restrict__ beta,
    float* __restrict__ out)
{
    const int row = blockIdx.x;
    const int tid = threadIdx.x;
    const int lane = tid & 31, wid = tid >> 5;
    size_t off = (size_t)row * Dq + tid * 4;
    float4 v = *(float4*)&out[off];

    __shared__ float ws[8];
    float s = v.x + v.y + v.z + v.w;
#pragma unroll
    for (int o = 16; o > 0; o >>= 1) s += __shfl_xor_sync(0xFFFFFFFFu, s, o);
    if (lane == 0) ws[wid] = s;
    __syncthreads();
    float tot = 0.f;
#pragma unroll
    for (int i = 0; i < 8; i++) tot += ws[i];
    float mu = tot * (1.f / Dq);
    __syncthreads();

    float d0 = v.x - mu, d1 = v.y - mu, d2 = v.z - mu, d3 = v.w - mu;
    float q = d0 * d0 + d1 * d1 + d2 * d2 + d3 * d3;
#pragma unroll
    for (int o = 16; o > 0; o >>= 1) q += __shfl_xor_sync(0xFFFFFFFFu, q, o);
    if (lane == 0) ws[wid] = q;
    __syncthreads();
    float tq = 0.f;
#pragma unroll
    for (int i = 0; i < 8; i++) tq += ws[i];
    float rstd = rsqrtf(tq * (1.f / Dq) + 1e-5f);

    int d = tid * 4;
    float4 g = *(const float4*)&gamma[d];
    float4 be = *(const float4*)&beta[d];
    float4 o;
    o.x = d0 * rstd * g.x + be.x;
    o.y = d1 * rstd * g.y + be.y;
    o.z = d2 * rstd * g.z + be.z;
    o.w = d3 * rstd * g.w + be.w;
    *(float4*)&out[off] = o;
}

extern "C" void kernel_launch(void* const* d_in, const int* in_sizes, int n_in,
                              void* d_out, int out_size)
{
    const float* x     = (const float*)d_in[0];
    const float* Wd    = (const float*)d_in[1];
    const float* bd    = (const float*)d_in[2];
    const float* Wb    = (const float*)d_in[3];
    const float* bb    = (const float*)d_in[4];
    const float* A_log = (const float*)d_in[5];
    const float* thr   = (const float*)d_in[6];
    const float* gamma = (const float*)d_in[7];
    const float* beta  = (const float*)d_in[8];

    float* out    = (float*)d_out;                    // [B,T,D] normalized output
    float* spikes = out + (size_t)Mq * Dq;            // [B,T,D] spikes

    dim3 grid(Dq / BN, Mq / BM);                      // (16, 128)
    fused_gemm_kernel<<<grid, 256>>>(x, Wd, bd, Wb, bb, A_log);
    scan_kernel<<<(Bq * Dq) / 32, 32>>>(thr, out, spikes);
    ln_kernel<<<Mq, 256>>>(gamma, beta, out);
}